// round 2
// baseline (speedup 1.0000x reference)
#include <cuda_runtime.h>
#include <cstdint>

// Problem constants: B=2, N=131072, M=512, G=20
#define BB 2
#define NN 131072
#define MM 512
#define GG 20
#define VV 8000
#define VOXINV 2.0f

#define NBLK 128                 // must be <= SM count (152) for co-residency
#define BPB  (NBLK / BB)         // 64 blocks per batch
#define NTHR 256
#define GROUPS (NN / 4)          // 32768 groups of 4 points per batch

// Device scratch (allocations forbidden)
__device__ float         g_pmin[NBLK * 3];     // per-block partial mins
__device__ float         g_minc[BB * 3];       // final per-batch mins
__device__ unsigned char g_mask[BB * VV];      // voxel needed?
__device__ float         g_acc[BB * VV * 10];  // cnt, sx..sz, xx,xy,xz,yy,yz,zz
__device__ unsigned int  g_bar_count;
__device__ unsigned int  g_bar_gen;

// --------------------------------------------------------------------------
// Software grid barrier (all NBLK blocks co-resident). Sense via generation.
// --------------------------------------------------------------------------
__device__ __forceinline__ void gbar() {
    __syncthreads();
    if (threadIdx.x == 0) {
        __threadfence();                                  // publish prior writes
        unsigned gen = atomicAdd(&g_bar_gen, 0u);         // read BEFORE arriving
        if (atomicAdd(&g_bar_count, 1u) == NBLK - 1) {
            atomicExch(&g_bar_count, 0u);
            __threadfence();
            atomicAdd(&g_bar_gen, 1u);                    // release
        } else {
            while (atomicAdd(&g_bar_gen, 0u) == gen) { __nanosleep(32); }
        }
    }
    __syncthreads();
}

__device__ __forceinline__ int voxel_of(float px, float py, float pz,
                                        float n0, float n1, float n2) {
    int vx = (int)floorf((px - n0) * VOXINV);
    int vy = (int)floorf((py - n1) * VOXINV);
    int vz = (int)floorf((pz - n2) * VOXINV);
    vx = min(max(vx, 0), GG - 1);
    vy = min(max(vy, 0), GG - 1);
    vz = min(max(vz, 0), GG - 1);
    return (vx * GG + vy) * GG + vz;
}

__global__ void __launch_bounds__(NTHR, 1)
fused_voxelizer(const float* __restrict__ x, const int* __restrict__ sidx,
                float* __restrict__ out) {
    const int bid = blockIdx.x, tid = threadIdx.x;
    const int t   = bid * NTHR + tid;
    const int b   = bid / BPB;            // batch this block serves
    const int br  = bid % BPB;            // block rank within batch
    const int lane = tid & 31, wid = tid >> 5;

    __shared__ float s_red[8 * 3];

    const float4* xb = (const float4*)(x + (size_t)b * NN * 3);

    // ===== Phase A: zero mask + per-block coordinate min (vectorized) =====
    {
        uint4* m4 = (uint4*)g_mask;       // 16000 bytes = 1000 uint4
        if (t < 1000) m4[t] = make_uint4(0u, 0u, 0u, 0u);

        float m0 = 3.4e38f, m1 = 3.4e38f, m2 = 3.4e38f;
        for (int g = br * NTHR + tid; g < GROUPS; g += BPB * NTHR) {
            float4 f0 = __ldg(xb + (size_t)g * 3 + 0);
            float4 f1 = __ldg(xb + (size_t)g * 3 + 1);
            float4 f2 = __ldg(xb + (size_t)g * 3 + 2);
            m0 = fminf(m0, fminf(fminf(f0.x, f0.w), fminf(f1.z, f2.y)));
            m1 = fminf(m1, fminf(fminf(f0.y, f1.x), fminf(f1.w, f2.z)));
            m2 = fminf(m2, fminf(fminf(f0.z, f1.y), fminf(f2.x, f2.w)));
        }
#pragma unroll
        for (int o = 16; o > 0; o >>= 1) {
            m0 = fminf(m0, __shfl_xor_sync(0xFFFFFFFFu, m0, o));
            m1 = fminf(m1, __shfl_xor_sync(0xFFFFFFFFu, m1, o));
            m2 = fminf(m2, __shfl_xor_sync(0xFFFFFFFFu, m2, o));
        }
        if (lane == 0) { s_red[wid*3+0] = m0; s_red[wid*3+1] = m1; s_red[wid*3+2] = m2; }
        __syncthreads();
        if (tid == 0) {
            float r0 = s_red[0], r1 = s_red[1], r2 = s_red[2];
#pragma unroll
            for (int w = 1; w < 8; w++) {
                r0 = fminf(r0, s_red[w*3+0]);
                r1 = fminf(r1, s_red[w*3+1]);
                r2 = fminf(r2, s_red[w*3+2]);
            }
            g_pmin[bid*3+0] = r0; g_pmin[bid*3+1] = r1; g_pmin[bid*3+2] = r2;
        }
    }
    gbar();

    // ===== Phase B: reduce partial mins (6 warps: batch x component) =====
    if (t < 192) {
        int w = t >> 5;                   // 0..5
        int rb = w / 3, c = w % 3;
        float m = 3.4e38f;
        for (int j = lane; j < BPB; j += 32)
            m = fminf(m, __ldcg(&g_pmin[(rb * BPB + j) * 3 + c]));
#pragma unroll
        for (int o = 16; o > 0; o >>= 1)
            m = fminf(m, __shfl_xor_sync(0xFFFFFFFFu, m, o));
        if (lane == 0) g_minc[rb * 3 + c] = m;
    }
    gbar();

    // ===== Phase C: mark sampled voxels + lazily zero their accumulators =====
    if (t < BB * MM) {
        int mb = t / MM;
        int i  = sidx[t];
        const float* p = x + ((size_t)mb * NN + i) * 3;
        float n0 = __ldcg(&g_minc[mb*3+0]);
        float n1 = __ldcg(&g_minc[mb*3+1]);
        float n2 = __ldcg(&g_minc[mb*3+2]);
        int gi = mb * VV + voxel_of(p[0], p[1], p[2], n0, n1, n2);
        g_mask[gi] = 1;                               // idempotent
        float* a = &g_acc[(size_t)gi * 10];
#pragma unroll
        for (int k = 0; k < 10; k++) a[k] = 0.0f;     // idempotent
    }
    gbar();

    // ===== Phase D: masked accumulation (x now L2-resident) =====
    {
        float n0 = __ldcg(&g_minc[b*3+0]);
        float n1 = __ldcg(&g_minc[b*3+1]);
        float n2 = __ldcg(&g_minc[b*3+2]);
        for (int g = br * NTHR + tid; g < GROUPS; g += BPB * NTHR) {
            float4 f0 = __ldg(xb + (size_t)g * 3 + 0);
            float4 f1 = __ldg(xb + (size_t)g * 3 + 1);
            float4 f2 = __ldg(xb + (size_t)g * 3 + 2);
            float px[4] = {f0.x, f0.w, f1.z, f2.y};
            float py[4] = {f0.y, f1.x, f1.w, f2.z};
            float pz[4] = {f0.z, f1.y, f2.x, f2.w};
            int vi[4];
            unsigned char mk[4];
#pragma unroll
            for (int k = 0; k < 4; k++)
                vi[k] = b * VV + voxel_of(px[k], py[k], pz[k], n0, n1, n2);
#pragma unroll
            for (int k = 0; k < 4; k++)
                mk[k] = __ldcg(&g_mask[vi[k]]);       // L2-scope: cross-SM coherent
#pragma unroll
            for (int k = 0; k < 4; k++) {
                if (mk[k]) {
                    float* a = &g_acc[(size_t)vi[k] * 10];
                    atomicAdd(a + 0, 1.0f);
                    atomicAdd(a + 1, px[k]);
                    atomicAdd(a + 2, py[k]);
                    atomicAdd(a + 3, pz[k]);
                    atomicAdd(a + 4, px[k] * px[k]);
                    atomicAdd(a + 5, px[k] * py[k]);
                    atomicAdd(a + 6, px[k] * pz[k]);
                    atomicAdd(a + 7, py[k] * py[k]);
                    atomicAdd(a + 8, py[k] * pz[k]);
                    atomicAdd(a + 9, pz[k] * pz[k]);
                }
            }
        }
    }
    gbar();

    // ===== Phase E: gather + finalize output (B, M, 12) =====
    if (t < BB * MM) {
        int mb = t / MM;
        int i  = sidx[t];
        const float* p = x + ((size_t)mb * NN + i) * 3;
        float n0 = __ldcg(&g_minc[mb*3+0]);
        float n1 = __ldcg(&g_minc[mb*3+1]);
        float n2 = __ldcg(&g_minc[mb*3+2]);
        int gi = mb * VV + voxel_of(p[0], p[1], p[2], n0, n1, n2);
        const float* a = &g_acc[(size_t)gi * 10];

        float c0 = __ldcg(a + 0);
        float s1 = __ldcg(a + 1), s2 = __ldcg(a + 2), s3 = __ldcg(a + 3);
        float q4 = __ldcg(a + 4), q5 = __ldcg(a + 5), q6 = __ldcg(a + 6);
        float q7 = __ldcg(a + 7), q8 = __ldcg(a + 8), q9 = __ldcg(a + 9);

        float inv = 1.0f / fmaxf(c0, 1.0f);
        float mx = s1 * inv, my = s2 * inv, mz = s3 * inv;
        float cxx = q4 * inv - mx * mx;
        float cxy = q5 * inv - mx * my;
        float cxz = q6 * inv - mx * mz;
        float cyy = q7 * inv - my * my;
        float cyz = q8 * inv - my * mz;
        float czz = q9 * inv - mz * mz;

        float* o = out + (size_t)t * 12;
        o[0] = mx;  o[1] = my;  o[2] = mz;
        o[3] = cxx; o[4] = cxy; o[5] = cxz;
        o[6] = cxy; o[7] = cyy; o[8] = cyz;
        o[9] = cxz; o[10] = cyz; o[11] = czz;
    }
}

// ---------------------------------------------------------------------------
extern "C" void kernel_launch(void* const* d_in, const int* in_sizes, int n_in,
                              void* d_out, int out_size) {
    const float* x    = (const float*)d_in[0];   // (B, N, 3) f32
    const int*   sidx = (const int*)d_in[1];     // (B, M) i32
    float*       out  = (float*)d_out;           // (B, M, 12) f32
    fused_voxelizer<<<NBLK, NTHR>>>(x, sidx, out);
}

// round 3
// speedup vs baseline: 1.9263x; 1.9263x over previous
#include <cuda_runtime.h>
#include <cstdint>
#include <math_constants.h>

// Problem constants: B=2, N=131072, M=512, G=20
#define BB 2
#define NN 131072
#define MM 512
#define GG 20
#define VV 8000
#define VOXINV 2.0f

#define GROUPS 32768            // NN/4 float4-groups per batch
#define BPB 128                 // blocks per batch (K1, K2)
#define NBLK (BB * BPB)         // 256 blocks
#define NTHR 256                // 256 groups/block -> exactly 1 group/thread
#define MASKW 250               // VV bits / 32

// Device scratch (allocations forbidden in kernel_launch)
__device__ float g_pmin[NBLK * 3];      // per-block partial mins (always rewritten)
__device__ float g_acc[BB * VV * 10];   // cnt, sx,sy,sz, xx,xy,xz,yy,yz,zz

__device__ __forceinline__ int voxel_of(float px, float py, float pz,
                                        float n0, float n1, float n2) {
    int vx = (int)floorf((px - n0) * VOXINV);
    int vy = (int)floorf((py - n1) * VOXINV);
    int vz = (int)floorf((pz - n2) * VOXINV);
    vx = min(max(vx, 0), GG - 1);
    vy = min(max(vy, 0), GG - 1);
    vz = min(max(vz, 0), GG - 1);
    return (vx * GG + vy) * GG + vz;
}

// Reduce this batch's 128 partial mins with warps 0..2 (one component each).
// Result in s_min[3]. Must be followed by __syncthreads() at call site.
__device__ __forceinline__ void reduce_min_smem(int b, int tid, float* s_min) {
    int w = tid >> 5, lane = tid & 31;
    if (w < 3) {
        float m = CUDART_INF_F;
#pragma unroll
        for (int j = 0; j < BPB; j += 32)
            m = fminf(m, g_pmin[(b * BPB + j + lane) * 3 + w]);
#pragma unroll
        for (int o = 16; o > 0; o >>= 1)
            m = fminf(m, __shfl_xor_sync(0xFFFFFFFFu, m, o));
        if (lane == 0) s_min[w] = m;
    }
}

// ============================================================================
// K1: zero accumulators + per-block coordinate min (float4, 1 group/thread)
// ============================================================================
__global__ void __launch_bounds__(NTHR)
k1_min(const float* __restrict__ x) {
    const int bid = blockIdx.x, tid = threadIdx.x;
    const int b = bid >> 7, br = bid & (BPB - 1);
    const int lane = tid & 31, w = tid >> 5;
    __shared__ float s_red[8 * 3];

    // zero g_acc: 160k floats = 40960 uint4, 160 per block
    {
        uint4* a4 = (uint4*)g_acc;
        if (tid < 160) a4[bid * 160 + tid] = make_uint4(0u, 0u, 0u, 0u);
    }

    // one group of 4 points per thread: 3 independent float4 loads
    const float4* xb = (const float4*)(x + (size_t)b * NN * 3);
    int g = br * NTHR + tid;
    float4 f0 = __ldg(xb + (size_t)g * 3 + 0);
    float4 f1 = __ldg(xb + (size_t)g * 3 + 1);
    float4 f2 = __ldg(xb + (size_t)g * 3 + 2);
    float m0 = fminf(fminf(f0.x, f0.w), fminf(f1.z, f2.y));
    float m1 = fminf(fminf(f0.y, f1.x), fminf(f1.w, f2.z));
    float m2 = fminf(fminf(f0.z, f1.y), fminf(f2.x, f2.w));
#pragma unroll
    for (int o = 16; o > 0; o >>= 1) {
        m0 = fminf(m0, __shfl_xor_sync(0xFFFFFFFFu, m0, o));
        m1 = fminf(m1, __shfl_xor_sync(0xFFFFFFFFu, m1, o));
        m2 = fminf(m2, __shfl_xor_sync(0xFFFFFFFFu, m2, o));
    }
    if (lane == 0) { s_red[w*3+0] = m0; s_red[w*3+1] = m1; s_red[w*3+2] = m2; }
    __syncthreads();
    if (tid == 0) {
        float r0 = s_red[0], r1 = s_red[1], r2 = s_red[2];
#pragma unroll
        for (int k = 1; k < 8; k++) {
            r0 = fminf(r0, s_red[k*3+0]);
            r1 = fminf(r1, s_red[k*3+1]);
            r2 = fminf(r2, s_red[k*3+2]);
        }
        g_pmin[bid*3+0] = r0; g_pmin[bid*3+1] = r1; g_pmin[bid*3+2] = r2;
    }
}

// ============================================================================
// K2: per-block smem mark (from sampled points) + masked accumulation.
// ============================================================================
__global__ void __launch_bounds__(NTHR)
k2_accum(const float* __restrict__ x, const int* __restrict__ sidx) {
    const int bid = blockIdx.x, tid = threadIdx.x;
    const int b = bid >> 7, br = bid & (BPB - 1);
    __shared__ float s_min[3];
    __shared__ unsigned int s_mask[MASKW];

    if (tid < MASKW) s_mask[tid] = 0u;
    reduce_min_smem(b, tid, s_min);
    __syncthreads();
    const float n0 = s_min[0], n1 = s_min[1], n2 = s_min[2];

    // Issue this thread's point-group loads EARLY (independent of mark work)
    const float4* xb = (const float4*)(x + (size_t)b * NN * 3);
    int g = br * NTHR + tid;
    float4 f0 = __ldg(xb + (size_t)g * 3 + 0);
    float4 f1 = __ldg(xb + (size_t)g * 3 + 1);
    float4 f2 = __ldg(xb + (size_t)g * 3 + 2);

    // Mark: 512 sampled points, 2 per thread (x gathers hit L2 after K1)
#pragma unroll
    for (int j = tid; j < MM; j += NTHR) {
        int i = __ldg(sidx + b * MM + j);
        const float* p = x + ((size_t)b * NN + i) * 3;
        int v = voxel_of(__ldg(p), __ldg(p + 1), __ldg(p + 2), n0, n1, n2);
        atomicOr(&s_mask[v >> 5], 1u << (v & 31));
    }
    __syncthreads();

    // Accumulate the 4 points of this thread's group
    float px[4] = {f0.x, f0.w, f1.z, f2.y};
    float py[4] = {f0.y, f1.x, f1.w, f2.z};
    float pz[4] = {f0.z, f1.y, f2.x, f2.w};
#pragma unroll
    for (int k = 0; k < 4; k++) {
        int v = voxel_of(px[k], py[k], pz[k], n0, n1, n2);
        if (s_mask[v >> 5] & (1u << (v & 31))) {
            float* a = &g_acc[(size_t)(b * VV + v) * 10];
            atomicAdd(a + 0, 1.0f);
            atomicAdd(a + 1, px[k]);
            atomicAdd(a + 2, py[k]);
            atomicAdd(a + 3, pz[k]);
            atomicAdd(a + 4, px[k] * px[k]);
            atomicAdd(a + 5, px[k] * py[k]);
            atomicAdd(a + 6, px[k] * pz[k]);
            atomicAdd(a + 7, py[k] * py[k]);
            atomicAdd(a + 8, py[k] * pz[k]);
            atomicAdd(a + 9, pz[k] * pz[k]);
        }
    }
}

// ============================================================================
// K3: gather stats at sampled voxels, finalize mean + covariance (B, M, 12)
// grid = 4 blocks x 256; blocks 0,1 -> batch 0; blocks 2,3 -> batch 1.
// ============================================================================
__global__ void __launch_bounds__(NTHR)
k3_out(const float* __restrict__ x, const int* __restrict__ sidx,
       float* __restrict__ out) {
    const int bid = blockIdx.x, tid = threadIdx.x;
    const int b = bid >> 1;
    __shared__ float s_min[3];
    reduce_min_smem(b, tid, s_min);
    __syncthreads();

    const int t = bid * NTHR + tid;            // 0..1023 == b*MM + j
    const int i = __ldg(sidx + t);
    const float* p = x + ((size_t)b * NN + i) * 3;
    const int v = voxel_of(__ldg(p), __ldg(p + 1), __ldg(p + 2),
                           s_min[0], s_min[1], s_min[2]);
    const float* a = &g_acc[(size_t)(b * VV + v) * 10];

    float c0 = a[0];
    float inv = 1.0f / fmaxf(c0, 1.0f);
    float mx = a[1] * inv, my = a[2] * inv, mz = a[3] * inv;
    float cxx = a[4] * inv - mx * mx;
    float cxy = a[5] * inv - mx * my;
    float cxz = a[6] * inv - mx * mz;
    float cyy = a[7] * inv - my * my;
    float cyz = a[8] * inv - my * mz;
    float czz = a[9] * inv - mz * mz;

    float* o = out + (size_t)t * 12;
    o[0] = mx;  o[1] = my;  o[2] = mz;
    o[3] = cxx; o[4] = cxy; o[5] = cxz;
    o[6] = cxy; o[7] = cyy; o[8] = cyz;
    o[9] = cxz; o[10] = cyz; o[11] = czz;
}

// ---------------------------------------------------------------------------
extern "C" void kernel_launch(void* const* d_in, const int* in_sizes, int n_in,
                              void* d_out, int out_size) {
    const float* x    = (const float*)d_in[0];   // (B, N, 3) f32
    const int*   sidx = (const int*)d_in[1];     // (B, M) i32
    float*       out  = (float*)d_out;           // (B, M, 12) f32

    k1_min<<<NBLK, NTHR>>>(x);
    k2_accum<<<NBLK, NTHR>>>(x, sidx);
    k3_out<<<4, NTHR>>>(x, sidx, out);
}